// round 13
// baseline (speedup 1.0000x reference)
#include <cuda_runtime.h>
#include <cuda.h>
#include <cstdint>

// ---------------- scratch (no allocations allowed) ----------------
#define MAX_BLOCKS 2048
__device__ float g_partials[MAX_BLOCKS];
__device__ unsigned int g_ticket = 0;   // last block wraps it back to 0

// ---------------- small PTX helpers ----------------
__device__ __forceinline__ uint32_t smem_u32(const void* p) {
    uint32_t a;
    asm("{ .reg .u64 t; cvta.to.shared.u64 t, %1; cvt.u32.u64 %0, t; }"
        : "=r"(a) : "l"(p));
    return a;
}
#define MBARRIER_INIT(addr, cnt) \
    asm volatile("mbarrier.init.shared.b64 [%0], %1;" :: "r"(addr), "r"(cnt) : "memory")
#define MBARRIER_EXPECT_TX(addr, bytes) \
    asm volatile("mbarrier.arrive.expect_tx.shared.b64 _, [%0], %1;" :: "r"(addr), "r"(bytes) : "memory")
__device__ __forceinline__ void mbar_wait(uint32_t mbar, uint32_t parity) {
    asm volatile(
        "{\n\t"
        ".reg .pred P1;\n\t"
        "WAIT_LOOP_%=:\n\t"
        "mbarrier.try_wait.parity.acquire.cta.shared::cta.b64 P1, [%0], %1, 0x989680;\n\t"
        "@P1 bra.uni WAIT_DONE_%=;\n\t"
        "bra.uni WAIT_LOOP_%=;\n\t"
        "WAIT_DONE_%=:\n\t"
        "}"
        :: "r"(mbar), "r"(parity) : "memory");
}
// TMA tile::gather4 — fetch 4 rows (16B each, boxDim={4,1}) into SMEM (64B).
// dst MUST be 128B aligned.
__device__ __forceinline__ void tma_gather4(uint32_t dst_smem, const void* tmap,
                                            int r0, int r1, int r2, int r3,
                                            uint32_t mbar) {
    asm volatile(
        "cp.async.bulk.tensor.2d.shared::cta.global.tile::gather4.mbarrier::complete_tx::bytes "
        "[%0], [%1, {%2, %3, %4, %5, %6}], [%7];"
        :: "r"(dst_smem), "l"(tmap), "r"(0), "r"(r0), "r"(r1), "r"(r2), "r"(r3),
           "r"(mbar)
        : "memory");
}

// ---------------- shared reduction epilogue ----------------
#define REDUCE_EPILOGUE(acc, out, inv_p)                                        \
    do {                                                                        \
        _Pragma("unroll")                                                       \
        for (int off = 16; off > 0; off >>= 1)                                  \
            acc += __shfl_down_sync(0xffffffffu, acc, off);                     \
        __shared__ float warp_sums_[8];                                         \
        int lane_ = threadIdx.x & 31;                                           \
        int wid_  = threadIdx.x >> 5;                                           \
        if (lane_ == 0) warp_sums_[wid_] = acc;                                 \
        __syncthreads();                                                        \
        __shared__ bool is_last_;                                               \
        if (wid_ == 0) {                                                        \
            float v = (lane_ < 8) ? warp_sums_[lane_] : 0.0f;                   \
            _Pragma("unroll")                                                   \
            for (int off = 4; off > 0; off >>= 1)                               \
                v += __shfl_down_sync(0xffffffffu, v, off);                     \
            if (lane_ == 0) {                                                   \
                g_partials[blockIdx.x] = v;                                     \
                __threadfence();                                                \
                unsigned int done = atomicInc(&g_ticket, gridDim.x - 1);        \
                is_last_ = (done == gridDim.x - 1);                             \
            }                                                                   \
        }                                                                       \
        __syncthreads();                                                        \
        if (is_last_) {                                                         \
            double s = 0.0;                                                     \
            for (int i = threadIdx.x; i < (int)gridDim.x; i += blockDim.x)      \
                s += (double)g_partials[i];                                     \
            __shared__ double dsums_[8];                                        \
            _Pragma("unroll")                                                   \
            for (int off = 16; off > 0; off >>= 1)                              \
                s += __shfl_down_sync(0xffffffffu, s, off);                     \
            if (lane_ == 0) dsums_[wid_] = s;                                   \
            __syncthreads();                                                    \
            if (wid_ == 0) {                                                    \
                double t = (lane_ < 8) ? dsums_[lane_] : 0.0;                   \
                _Pragma("unroll")                                               \
                for (int off = 4; off > 0; off >>= 1)                           \
                    t += __shfl_down_sync(0xffffffffu, t, off);                 \
                if (lane_ == 0) out[0] = (float)(t * (double)inv_p);            \
            }                                                                   \
        }                                                                       \
    } while (0)

// ====== hybrid kernel: 5 unrolled LDG warps + 3 TMA warps ======
// Model (fits R7-R12): LDG rate 0.0081/warp non-unrolled, ~0.016/warp with
// 2x unroll, ceiling 0.476 edges/cyc/SM; TMA rate 0.098@12w .. 0.148@24w.
// 5 LDG warps x 6 CTAs = 30 warps/SM, 2x unrolled -> ceiling-bound (~0.476).
// 3 TMA warps x 6 CTAs = 18 warps/SM -> ~0.125. Split 80/20.
#define LDG_WARPS 5
#define TMA_WARPS 3
#define STRIDE_PER_LANE 128  // gather4 dst must be 128B aligned
#define STAGE_BYTES (32 * STRIDE_PER_LANE)   // 4096 per warp-stage

__global__ void __launch_bounds__(256)
mde_hybrid_kernel(const __grid_constant__ CUtensorMap tmap,
                  const float4* __restrict__ X,
                  const int4* __restrict__ epairs,
                  const float2* __restrict__ wpairs,
                  int npairs_ldg,          // int4 pairs in LDG region
                  int nb_tma,              // 64-edge batches in TMA region
                  const int2* __restrict__ etail,
                  const float* __restrict__ wtail,
                  int tail_lo, int tail_hi, // leftover single edges [lo, hi)
                  float* __restrict__ out, float inv_p) {
    __shared__ __align__(8)   uint64_t mbar[TMA_WARPS * 2];
    __shared__ __align__(128) char tbuf[TMA_WARPS][2][STAGE_BYTES];

    int tid  = threadIdx.x;
    int lane = tid & 31;
    int wid  = tid >> 5;
    float acc = 0.0f;

    if (wid < LDG_WARPS) {
        // ---------- LDG path, 2x unrolled (R4-proven structure, 32 regs) ----------
        int t = blockIdx.x * (LDG_WARPS * 32) + wid * 32 + lane;
        int stride = gridDim.x * (LDG_WARPS * 32);
        int k = t;
        for (; k + stride < npairs_ldg; k += 2 * stride) {
            int4   eA = __ldcs(&epairs[k]);
            int4   eB = __ldcs(&epairs[k + stride]);
            float2 wA = __ldcs(&wpairs[k]);
            float2 wB = __ldcs(&wpairs[k + stride]);
            float4 a0 = __ldg(&X[eA.x]);
            float4 b0 = __ldg(&X[eA.y]);
            float4 a1 = __ldg(&X[eA.z]);
            float4 b1 = __ldg(&X[eA.w]);
            float4 a2 = __ldg(&X[eB.x]);
            float4 b2 = __ldg(&X[eB.y]);
            float4 a3 = __ldg(&X[eB.z]);
            float4 b3 = __ldg(&X[eB.w]);
            float dx0 = a0.x - b0.x, dy0 = a0.y - b0.y, dz0 = a0.z - b0.z, dw0 = a0.w - b0.w;
            float dx1 = a1.x - b1.x, dy1 = a1.y - b1.y, dz1 = a1.z - b1.z, dw1 = a1.w - b1.w;
            float dx2 = a2.x - b2.x, dy2 = a2.y - b2.y, dz2 = a2.z - b2.z, dw2 = a2.w - b2.w;
            float dx3 = a3.x - b3.x, dy3 = a3.y - b3.y, dz3 = a3.z - b3.z, dw3 = a3.w - b3.w;
            acc = fmaf(wA.x, dx0 * dx0 + dy0 * dy0 + dz0 * dz0 + dw0 * dw0, acc);
            acc = fmaf(wA.y, dx1 * dx1 + dy1 * dy1 + dz1 * dz1 + dw1 * dw1, acc);
            acc = fmaf(wB.x, dx2 * dx2 + dy2 * dy2 + dz2 * dz2 + dw2 * dw2, acc);
            acc = fmaf(wB.y, dx3 * dx3 + dy3 * dy3 + dz3 * dz3 + dw3 * dw3, acc);
        }
        for (; k < npairs_ldg; k += stride) {
            int4   e = __ldcs(&epairs[k]);
            float2 w = __ldcs(&wpairs[k]);
            float4 a0 = __ldg(&X[e.x]);
            float4 b0 = __ldg(&X[e.y]);
            float4 a1 = __ldg(&X[e.z]);
            float4 b1 = __ldg(&X[e.w]);
            float dx0 = a0.x - b0.x, dy0 = a0.y - b0.y, dz0 = a0.z - b0.z, dw0 = a0.w - b0.w;
            float dx1 = a1.x - b1.x, dy1 = a1.y - b1.y, dz1 = a1.z - b1.z, dw1 = a1.w - b1.w;
            acc = fmaf(w.x, dx0 * dx0 + dy0 * dy0 + dz0 * dz0 + dw0 * dw0, acc);
            acc = fmaf(w.y, dx1 * dx1 + dy1 * dy1 + dz1 * dz1 + dw1 * dw1, acc);
        }
        // leftover single edges (at most 1)
        for (int q = tail_lo + t; q < tail_hi; q += stride) {
            int2 e = __ldg(&etail[q]);
            float4 a = __ldg(&X[e.x]);
            float4 b = __ldg(&X[e.y]);
            float dx = a.x - b.x, dy = a.y - b.y, dz = a.z - b.z, dw = a.w - b.w;
            acc = fmaf(__ldg(&wtail[q]), dx * dx + dy * dy + dz * dz + dw * dw, acc);
        }
    } else {
        // ---------- TMA gather4 path (R7-proven 2-stage double buffer) ----------
        int tw = wid - LDG_WARPS;            // 0..2
        uint32_t mb0 = smem_u32(&mbar[tw * 2 + 0]);
        uint32_t mb1 = smem_u32(&mbar[tw * 2 + 1]);
        uint32_t buf0 = smem_u32(&tbuf[tw][0][0]) + (uint32_t)lane * STRIDE_PER_LANE;
        uint32_t buf1 = smem_u32(&tbuf[tw][1][0]) + (uint32_t)lane * STRIDE_PER_LANE;
        if (lane == 0) {
            MBARRIER_INIT(mb0, 1);
            MBARRIER_INIT(mb1, 1);
            asm volatile("fence.proxy.async.shared::cta;" ::: "memory");
        }
        __syncwarp();

        int W  = gridDim.x * TMA_WARPS;
        int gw = blockIdx.x * TMA_WARPS + tw;
        int nlocal = (gw < nb_tma) ? ((nb_tma - 1 - gw) / W + 1) : 0;

        float2 w0, w1;
        auto issue = [&](int bl, uint32_t mb, uint32_t bufaddr, float2& wreg) {
            int gb = gw + bl * W;
            int idx = npairs_ldg + gb * 32 + lane;   // int4 index into edge array
            if (lane == 0) MBARRIER_EXPECT_TX(mb, 32 * 64);
            __syncwarp();
            int4 e = __ldcs(&epairs[idx]);
            wreg = __ldcs(&wpairs[idx]);
            tma_gather4(bufaddr, (const void*)&tmap, e.x, e.y, e.z, e.w, mb);
        };
        auto consume = [&](uint32_t bufaddr, float2 w) {
            const float4* blk = (const float4*)__cvta_shared_to_generic(bufaddr);
            float4 a0 = blk[0], b0 = blk[1], a1 = blk[2], b1 = blk[3];
            float dx0 = a0.x - b0.x, dy0 = a0.y - b0.y, dz0 = a0.z - b0.z, dw0 = a0.w - b0.w;
            float dx1 = a1.x - b1.x, dy1 = a1.y - b1.y, dz1 = a1.z - b1.z, dw1 = a1.w - b1.w;
            acc = fmaf(w.x, dx0 * dx0 + dy0 * dy0 + dz0 * dz0 + dw0 * dw0, acc);
            acc = fmaf(w.y, dx1 * dx1 + dy1 * dy1 + dz1 * dz1 + dw1 * dw1, acc);
        };

        if (nlocal > 0) issue(0, mb0, buf0, w0);
        int ph0 = 0, ph1 = 0, b = 0;
        while (b < nlocal) {
            if (b + 1 < nlocal) issue(b + 1, mb1, buf1, w1);
            mbar_wait(mb0, ph0); ph0 ^= 1;
            consume(buf0, w0);
            if (++b >= nlocal) break;
            if (b + 1 < nlocal) issue(b + 1, mb0, buf0, w0);
            mbar_wait(mb1, ph1); ph1 ^= 1;
            consume(buf1, w1);
            ++b;
        }
    }

    REDUCE_EPILOGUE(acc, out, inv_p);
}

// ================= fallback LDG kernel (proven 80.6us) =================
__global__ void __launch_bounds__(256)
mde_ldg_kernel(const float4* __restrict__ X,
               const int4* __restrict__ epairs,
               const float2* __restrict__ wpairs,
               int npairs,
               const int2* __restrict__ etail,
               const float* __restrict__ wtail,
               int p,
               float* __restrict__ out, float inv_p) {
    float acc = 0.0f;
    int stride = gridDim.x * blockDim.x;
    int tid = blockIdx.x * blockDim.x + threadIdx.x;
    for (int k = tid; k < npairs; k += stride) {
        int4   e = __ldcs(&epairs[k]);
        float2 w = __ldcs(&wpairs[k]);
        float4 a0 = __ldg(&X[e.x]);
        float4 b0 = __ldg(&X[e.y]);
        float4 a1 = __ldg(&X[e.z]);
        float4 b1 = __ldg(&X[e.w]);
        float dx0 = a0.x - b0.x, dy0 = a0.y - b0.y, dz0 = a0.z - b0.z, dw0 = a0.w - b0.w;
        float dx1 = a1.x - b1.x, dy1 = a1.y - b1.y, dz1 = a1.z - b1.z, dw1 = a1.w - b1.w;
        acc = fmaf(w.x, dx0 * dx0 + dy0 * dy0 + dz0 * dz0 + dw0 * dw0, acc);
        acc = fmaf(w.y, dx1 * dx1 + dy1 * dy1 + dz1 * dz1 + dw1 * dw1, acc);
    }
    int tail_base = npairs * 2;
    for (int k = tail_base + tid; k < p; k += stride) {
        int2 e = __ldg(&etail[k]);
        float4 a = __ldg(&X[e.x]);
        float4 b = __ldg(&X[e.y]);
        float dx = a.x - b.x, dy = a.y - b.y, dz = a.z - b.z, dw = a.w - b.w;
        acc = fmaf(__ldg(&wtail[k]), dx * dx + dy * dy + dz * dz + dw * dw, acc);
    }
    REDUCE_EPILOGUE(acc, out, inv_p);
}

// ================= host =================
extern "C" void kernel_launch(void* const* d_in, const int* in_sizes, int n_in,
                              void* d_out, int out_size) {
    const float4* X     = (const float4*)d_in[0];
    const int*    edges = (const int*)d_in[1];
    const float*  w     = (const float*)d_in[2];
    float*        out   = (float*)d_out;

    int p = in_sizes[2];
    float inv_p = 1.0f / (float)p;

    // Encode gather4 tensor map for X: f32 rank-2, global [4 x n_items], box {4,1}.
    bool tma_ok = false;
    CUtensorMap tmap;
    {
        typedef CUresult (*EncodeFn)(CUtensorMap*, CUtensorMapDataType, cuuint32_t,
                                     void*, const cuuint64_t*, const cuuint64_t*,
                                     const cuuint32_t*, const cuuint32_t*,
                                     CUtensorMapInterleave, CUtensorMapSwizzle,
                                     CUtensorMapL2promotion, CUtensorMapFloatOOBfill);
        EncodeFn fn = nullptr;
        cudaDriverEntryPointQueryResult qres;
        if (cudaGetDriverEntryPointByVersion("cuTensorMapEncodeTiled", (void**)&fn,
                                             12000, cudaEnableDefault, &qres) == cudaSuccess
            && fn != nullptr) {
            cuuint64_t gdim[2] = {4ull, (cuuint64_t)(in_sizes[0] / 4)};
            cuuint64_t gstr[1] = {16ull};
            cuuint32_t box[2]  = {4u, 1u};
            cuuint32_t est[2]  = {1u, 1u};
            CUresult r = fn(&tmap, CU_TENSOR_MAP_DATA_TYPE_FLOAT32, 2, (void*)X,
                            gdim, gstr, box, est,
                            CU_TENSOR_MAP_INTERLEAVE_NONE,
                            CU_TENSOR_MAP_SWIZZLE_NONE,
                            CU_TENSOR_MAP_L2_PROMOTION_L2_128B,
                            CU_TENSOR_MAP_FLOAT_OOB_FILL_NONE);
            tma_ok = (r == CUDA_SUCCESS);
        }
    }

    if (tma_ok && p >= 2048) {
        int blocks = 888;   // 148 SMs x 6 CTAs (smem ~25KB/CTA, regs <= 42)
        // 80/20 split: LDG ceiling 0.476 vs TMA@18w ~0.12 edges/cyc/SM.
        long long tma_share = (long long)p / 5;
        int nb_tma = (int)(tma_share / 64);
        int tma_edges = nb_tma * 64;
        int L = p - tma_edges;              // LDG region [0, L)
        int npairs_ldg = L / 2;
        int tail_lo = npairs_ldg * 2;       // leftover single edges in [tail_lo, L)
        mde_hybrid_kernel<<<blocks, 256>>>(tmap, X,
                                           (const int4*)edges, (const float2*)w,
                                           npairs_ldg, nb_tma,
                                           (const int2*)edges, w, tail_lo, L,
                                           out, inv_p);
    } else {
        int blocks = 1184;
        int npairs = p / 2;
        mde_ldg_kernel<<<blocks, 256>>>(X,
                                        (const int4*)edges, (const float2*)w, npairs,
                                        (const int2*)edges, w, p,
                                        out, inv_p);
    }
}

// round 14
// speedup vs baseline: 1.6118x; 1.6118x over previous
#include <cuda_runtime.h>
#include <cuda.h>
#include <cstdint>

// ---------------- scratch (no allocations allowed) ----------------
#define MAX_BLOCKS 2048
__device__ float g_partials[MAX_BLOCKS];
__device__ unsigned int g_ticket = 0;   // last block wraps it back to 0

// ---------------- small PTX helpers ----------------
__device__ __forceinline__ uint32_t smem_u32(const void* p) {
    uint32_t a;
    asm("{ .reg .u64 t; cvta.to.shared.u64 t, %1; cvt.u32.u64 %0, t; }"
        : "=r"(a) : "l"(p));
    return a;
}
#define MBARRIER_INIT(addr, cnt) \
    asm volatile("mbarrier.init.shared.b64 [%0], %1;" :: "r"(addr), "r"(cnt) : "memory")
#define MBARRIER_EXPECT_TX(addr, bytes) \
    asm volatile("mbarrier.arrive.expect_tx.shared.b64 _, [%0], %1;" :: "r"(addr), "r"(bytes) : "memory")
__device__ __forceinline__ void mbar_wait(uint32_t mbar, uint32_t parity) {
    asm volatile(
        "{\n\t"
        ".reg .pred P1;\n\t"
        "WAIT_LOOP_%=:\n\t"
        "mbarrier.try_wait.parity.acquire.cta.shared::cta.b64 P1, [%0], %1, 0x989680;\n\t"
        "@P1 bra.uni WAIT_DONE_%=;\n\t"
        "bra.uni WAIT_LOOP_%=;\n\t"
        "WAIT_DONE_%=:\n\t"
        "}"
        :: "r"(mbar), "r"(parity) : "memory");
}
// TMA tile::gather4 — fetch 4 rows (16B each, boxDim={4,1}) into SMEM (64B).
// dst MUST be 128B aligned.
__device__ __forceinline__ void tma_gather4(uint32_t dst_smem, const void* tmap,
                                            int r0, int r1, int r2, int r3,
                                            uint32_t mbar) {
    asm volatile(
        "cp.async.bulk.tensor.2d.shared::cta.global.tile::gather4.mbarrier::complete_tx::bytes "
        "[%0], [%1, {%2, %3, %4, %5, %6}], [%7];"
        :: "r"(dst_smem), "l"(tmap), "r"(0), "r"(r0), "r"(r1), "r"(r2), "r"(r3),
           "r"(mbar)
        : "memory");
}

// ---------------- shared reduction epilogue ----------------
#define REDUCE_EPILOGUE(acc, out, inv_p)                                        \
    do {                                                                        \
        _Pragma("unroll")                                                       \
        for (int off = 16; off > 0; off >>= 1)                                  \
            acc += __shfl_down_sync(0xffffffffu, acc, off);                     \
        __shared__ float warp_sums_[8];                                         \
        int lane_ = threadIdx.x & 31;                                           \
        int wid_  = threadIdx.x >> 5;                                           \
        if (lane_ == 0) warp_sums_[wid_] = acc;                                 \
        __syncthreads();                                                        \
        __shared__ bool is_last_;                                               \
        if (wid_ == 0) {                                                        \
            float v = (lane_ < 8) ? warp_sums_[lane_] : 0.0f;                   \
            _Pragma("unroll")                                                   \
            for (int off = 4; off > 0; off >>= 1)                               \
                v += __shfl_down_sync(0xffffffffu, v, off);                     \
            if (lane_ == 0) {                                                   \
                g_partials[blockIdx.x] = v;                                     \
                __threadfence();                                                \
                unsigned int done = atomicInc(&g_ticket, gridDim.x - 1);        \
                is_last_ = (done == gridDim.x - 1);                             \
            }                                                                   \
        }                                                                       \
        __syncthreads();                                                        \
        if (is_last_) {                                                         \
            double s = 0.0;                                                     \
            for (int i = threadIdx.x; i < (int)gridDim.x; i += blockDim.x)      \
                s += (double)g_partials[i];                                     \
            __shared__ double dsums_[8];                                        \
            _Pragma("unroll")                                                   \
            for (int off = 16; off > 0; off >>= 1)                              \
                s += __shfl_down_sync(0xffffffffu, s, off);                     \
            if (lane_ == 0) dsums_[wid_] = s;                                   \
            __syncthreads();                                                    \
            if (wid_ == 0) {                                                    \
                double t = (lane_ < 8) ? dsums_[lane_] : 0.0;                   \
                _Pragma("unroll")                                               \
                for (int off = 4; off > 0; off >>= 1)                           \
                    t += __shfl_down_sync(0xffffffffu, t, off);                 \
                if (lane_ == 0) out[0] = (float)(t * (double)inv_p);            \
            }                                                                   \
        }                                                                       \
    } while (0)

// ======= hybrid kernel: R8 structure at FULL occupancy (8 CTAs/SM) =======
// Warps 0-5 (75% of edges): LDG gathers. 48 warps/SM x 0.0083 = 0.40 e/cyc/SM.
// Warps 6-7 (25% of edges): TMA gather4, 64-edge batches, 2-stage double
// buffer. 16 warps/SM x 0.0082 = 0.13 e/cyc/SM. smem 17KB/CTA, 32 regs ->
// 8 CTAs/SM resident (the R7-R13 hybrids accidentally ran at 6).
#define LDG_WARPS 6
#define TMA_WARPS 2
#define STRIDE_PER_LANE 128  // gather4 dst must be 128B aligned
#define STAGE_BYTES (32 * STRIDE_PER_LANE)   // 4096 per warp-stage

__global__ void __launch_bounds__(256, 8)
mde_hybrid_kernel(const __grid_constant__ CUtensorMap tmap,
                  const float4* __restrict__ X,
                  const int4* __restrict__ epairs,
                  const float2* __restrict__ wpairs,
                  int npairs_ldg,          // int4 pairs in LDG region
                  int nb_tma,              // 64-edge batches in TMA region
                  const int2* __restrict__ etail,
                  const float* __restrict__ wtail,
                  int tail_lo, int tail_hi, // leftover single edges [lo, hi)
                  float* __restrict__ out, float inv_p) {
    __shared__ __align__(8)   uint64_t mbar[TMA_WARPS * 2];
    __shared__ __align__(128) char tbuf[TMA_WARPS][2][STAGE_BYTES];

    int tid  = threadIdx.x;
    int lane = tid & 31;
    int wid  = tid >> 5;
    float acc = 0.0f;

    if (wid < LDG_WARPS) {
        // ---------- LDG path ----------
        int t = blockIdx.x * (LDG_WARPS * 32) + wid * 32 + lane;
        int stride = gridDim.x * (LDG_WARPS * 32);
        for (int k = t; k < npairs_ldg; k += stride) {
            int4   e = __ldcs(&epairs[k]);
            float2 w = __ldcs(&wpairs[k]);
            float4 a0 = __ldg(&X[e.x]);
            float4 b0 = __ldg(&X[e.y]);
            float4 a1 = __ldg(&X[e.z]);
            float4 b1 = __ldg(&X[e.w]);
            float dx0 = a0.x - b0.x, dy0 = a0.y - b0.y, dz0 = a0.z - b0.z, dw0 = a0.w - b0.w;
            float dx1 = a1.x - b1.x, dy1 = a1.y - b1.y, dz1 = a1.z - b1.z, dw1 = a1.w - b1.w;
            acc = fmaf(w.x, dx0 * dx0 + dy0 * dy0 + dz0 * dz0 + dw0 * dw0, acc);
            acc = fmaf(w.y, dx1 * dx1 + dy1 * dy1 + dz1 * dz1 + dw1 * dw1, acc);
        }
        // leftover single edges (at most 1)
        for (int q = tail_lo + t; q < tail_hi; q += stride) {
            int2 e = __ldg(&etail[q]);
            float4 a = __ldg(&X[e.x]);
            float4 b = __ldg(&X[e.y]);
            float dx = a.x - b.x, dy = a.y - b.y, dz = a.z - b.z, dw = a.w - b.w;
            acc = fmaf(__ldg(&wtail[q]), dx * dx + dy * dy + dz * dz + dw * dw, acc);
        }
    } else {
        // ---------- TMA gather4 path (2-stage double buffer) ----------
        int tw = wid - LDG_WARPS;            // 0..1
        uint32_t mb0 = smem_u32(&mbar[tw * 2 + 0]);
        uint32_t mb1 = smem_u32(&mbar[tw * 2 + 1]);
        uint32_t buf0 = smem_u32(&tbuf[tw][0][0]) + (uint32_t)lane * STRIDE_PER_LANE;
        uint32_t buf1 = smem_u32(&tbuf[tw][1][0]) + (uint32_t)lane * STRIDE_PER_LANE;
        if (lane == 0) {
            MBARRIER_INIT(mb0, 1);
            MBARRIER_INIT(mb1, 1);
            asm volatile("fence.proxy.async.shared::cta;" ::: "memory");
        }
        __syncwarp();

        int W  = gridDim.x * TMA_WARPS;
        int gw = blockIdx.x * TMA_WARPS + tw;
        int nlocal = (gw < nb_tma) ? ((nb_tma - 1 - gw) / W + 1) : 0;

        float2 w0, w1;
        auto issue = [&](int bl, uint32_t mb, uint32_t bufaddr, float2& wreg) {
            int gb = gw + bl * W;
            int idx = npairs_ldg + gb * 32 + lane;   // int4 index into edge array
            if (lane == 0) MBARRIER_EXPECT_TX(mb, 32 * 64);
            __syncwarp();
            int4 e = __ldcs(&epairs[idx]);
            wreg = __ldcs(&wpairs[idx]);
            tma_gather4(bufaddr, (const void*)&tmap, e.x, e.y, e.z, e.w, mb);
        };
        auto consume = [&](uint32_t bufaddr, float2 w) {
            const float4* blk = (const float4*)__cvta_shared_to_generic(bufaddr);
            float4 a0 = blk[0], b0 = blk[1], a1 = blk[2], b1 = blk[3];
            float dx0 = a0.x - b0.x, dy0 = a0.y - b0.y, dz0 = a0.z - b0.z, dw0 = a0.w - b0.w;
            float dx1 = a1.x - b1.x, dy1 = a1.y - b1.y, dz1 = a1.z - b1.z, dw1 = a1.w - b1.w;
            acc = fmaf(w.x, dx0 * dx0 + dy0 * dy0 + dz0 * dz0 + dw0 * dw0, acc);
            acc = fmaf(w.y, dx1 * dx1 + dy1 * dy1 + dz1 * dz1 + dw1 * dw1, acc);
        };

        if (nlocal > 0) issue(0, mb0, buf0, w0);
        int ph0 = 0, ph1 = 0, b = 0;
        while (b < nlocal) {
            if (b + 1 < nlocal) issue(b + 1, mb1, buf1, w1);
            mbar_wait(mb0, ph0); ph0 ^= 1;
            consume(buf0, w0);
            if (++b >= nlocal) break;
            if (b + 1 < nlocal) issue(b + 1, mb0, buf0, w0);
            mbar_wait(mb1, ph1); ph1 ^= 1;
            consume(buf1, w1);
            ++b;
        }
    }

    REDUCE_EPILOGUE(acc, out, inv_p);
}

// ================= fallback LDG kernel (proven 80.6us) =================
__global__ void __launch_bounds__(256)
mde_ldg_kernel(const float4* __restrict__ X,
               const int4* __restrict__ epairs,
               const float2* __restrict__ wpairs,
               int npairs,
               const int2* __restrict__ etail,
               const float* __restrict__ wtail,
               int p,
               float* __restrict__ out, float inv_p) {
    float acc = 0.0f;
    int stride = gridDim.x * blockDim.x;
    int tid = blockIdx.x * blockDim.x + threadIdx.x;
    for (int k = tid; k < npairs; k += stride) {
        int4   e = __ldcs(&epairs[k]);
        float2 w = __ldcs(&wpairs[k]);
        float4 a0 = __ldg(&X[e.x]);
        float4 b0 = __ldg(&X[e.y]);
        float4 a1 = __ldg(&X[e.z]);
        float4 b1 = __ldg(&X[e.w]);
        float dx0 = a0.x - b0.x, dy0 = a0.y - b0.y, dz0 = a0.z - b0.z, dw0 = a0.w - b0.w;
        float dx1 = a1.x - b1.x, dy1 = a1.y - b1.y, dz1 = a1.z - b1.z, dw1 = a1.w - b1.w;
        acc = fmaf(w.x, dx0 * dx0 + dy0 * dy0 + dz0 * dz0 + dw0 * dw0, acc);
        acc = fmaf(w.y, dx1 * dx1 + dy1 * dy1 + dz1 * dz1 + dw1 * dw1, acc);
    }
    int tail_base = npairs * 2;
    for (int k = tail_base + tid; k < p; k += stride) {
        int2 e = __ldg(&etail[k]);
        float4 a = __ldg(&X[e.x]);
        float4 b = __ldg(&X[e.y]);
        float dx = a.x - b.x, dy = a.y - b.y, dz = a.z - b.z, dw = a.w - b.w;
        acc = fmaf(__ldg(&wtail[k]), dx * dx + dy * dy + dz * dz + dw * dw, acc);
    }
    REDUCE_EPILOGUE(acc, out, inv_p);
}

// ================= host =================
extern "C" void kernel_launch(void* const* d_in, const int* in_sizes, int n_in,
                              void* d_out, int out_size) {
    const float4* X     = (const float4*)d_in[0];
    const int*    edges = (const int*)d_in[1];
    const float*  w     = (const float*)d_in[2];
    float*        out   = (float*)d_out;

    int p = in_sizes[2];
    float inv_p = 1.0f / (float)p;

    // Encode gather4 tensor map for X: f32 rank-2, global [4 x n_items], box {4,1}.
    bool tma_ok = false;
    CUtensorMap tmap;
    {
        typedef CUresult (*EncodeFn)(CUtensorMap*, CUtensorMapDataType, cuuint32_t,
                                     void*, const cuuint64_t*, const cuuint64_t*,
                                     const cuuint32_t*, const cuuint32_t*,
                                     CUtensorMapInterleave, CUtensorMapSwizzle,
                                     CUtensorMapL2promotion, CUtensorMapFloatOOBfill);
        EncodeFn fn = nullptr;
        cudaDriverEntryPointQueryResult qres;
        if (cudaGetDriverEntryPointByVersion("cuTensorMapEncodeTiled", (void**)&fn,
                                             12000, cudaEnableDefault, &qres) == cudaSuccess
            && fn != nullptr) {
            cuuint64_t gdim[2] = {4ull, (cuuint64_t)(in_sizes[0] / 4)};
            cuuint64_t gstr[1] = {16ull};
            cuuint32_t box[2]  = {4u, 1u};
            cuuint32_t est[2]  = {1u, 1u};
            CUresult r = fn(&tmap, CU_TENSOR_MAP_DATA_TYPE_FLOAT32, 2, (void*)X,
                            gdim, gstr, box, est,
                            CU_TENSOR_MAP_INTERLEAVE_NONE,
                            CU_TENSOR_MAP_SWIZZLE_NONE,
                            CU_TENSOR_MAP_L2_PROMOTION_L2_128B,
                            CU_TENSOR_MAP_FLOAT_OOB_FILL_NONE);
            tma_ok = (r == CUDA_SUCCESS);
        }
    }

    if (tma_ok && p >= 2048) {
        int blocks = 1184;  // FULL occupancy: 148 SMs x 8 CTAs (17KB smem, 32 regs)
        if (blocks > MAX_BLOCKS) blocks = MAX_BLOCKS;
        // 75/25 split matches the 48:16 warp ratio at equal per-warp rates.
        int nb_tma = (p / 4) / 64;
        int tma_edges = nb_tma * 64;
        int L = p - tma_edges;              // LDG region [0, L)
        int npairs_ldg = L / 2;
        int tail_lo = npairs_ldg * 2;       // leftover single edges in [tail_lo, L)
        mde_hybrid_kernel<<<blocks, 256>>>(tmap, X,
                                           (const int4*)edges, (const float2*)w,
                                           npairs_ldg, nb_tma,
                                           (const int2*)edges, w, tail_lo, L,
                                           out, inv_p);
    } else {
        int blocks = 1184;
        int npairs = p / 2;
        mde_ldg_kernel<<<blocks, 256>>>(X,
                                        (const int4*)edges, (const float2*)w, npairs,
                                        (const int2*)edges, w, p,
                                        out, inv_p);
    }
}

// round 15
// speedup vs baseline: 1.7399x; 1.0795x over previous
#include <cuda_runtime.h>
#include <cstdint>

// ---------------- scratch (no allocations allowed) ----------------
#define MAX_BLOCKS 2048
__device__ float g_partials[MAX_BLOCKS];
__device__ unsigned int g_ticket = 0;   // last block wraps it back to 0
__device__ unsigned int g_ctr = 0;      // work-steal chunk counter; last block resets

#define CHUNK_PAIRS 256   // 512 edges per grabbed chunk; 8 iterations per lane

// Single fused kernel, warp-level dynamic work stealing:
//  - work = int4 edge-pairs, dispensed in CHUNK_PAIRS chunks via one global
//    atomic per warp-grab (lane 0 grabs, broadcast by shfl). Consecutive lanes
//    read consecutive int4 -> fully coalesced streams; gathers random (L2-hit).
//  - eliminates the static-partition tail: cross-CTA L1tex-queue contention
//    spreads CTA completion ~1.3x (B300 spr model); stealing bounds the
//    imbalance to one chunk per warp.
//  - fused reduction: block partials + ticket; last block reduces, writes the
//    mean, resets ticket (atomicInc wrap) and g_ctr (deterministic replays).
__global__ void __launch_bounds__(256)
mde_steal_kernel(const float4* __restrict__ X,
                 const int4* __restrict__ epairs,
                 const float2* __restrict__ wpairs,
                 int npairs,
                 int nchunks,
                 const int2* __restrict__ etail,
                 const float* __restrict__ wtail,
                 int p,
                 float* __restrict__ out, float inv_p) {
    int tid  = threadIdx.x;
    int lane = tid & 31;
    int wid  = tid >> 5;
    float acc = 0.0f;

    // ---- dynamic chunk loop ----
    for (;;) {
        unsigned int c;
        if (lane == 0) c = atomicAdd(&g_ctr, 1u);
        c = __shfl_sync(0xffffffffu, c, 0);
        if (c >= (unsigned int)nchunks) break;

        int base = (int)c * CHUNK_PAIRS;
        int end  = base + CHUNK_PAIRS;
        if (end > npairs) end = npairs;
        for (int k = base + lane; k < end; k += 32) {
            int4   e = __ldcs(&epairs[k]);
            float2 w = __ldcs(&wpairs[k]);
            float4 a0 = __ldg(&X[e.x]);
            float4 b0 = __ldg(&X[e.y]);
            float4 a1 = __ldg(&X[e.z]);
            float4 b1 = __ldg(&X[e.w]);
            float dx0 = a0.x - b0.x, dy0 = a0.y - b0.y, dz0 = a0.z - b0.z, dw0 = a0.w - b0.w;
            float dx1 = a1.x - b1.x, dy1 = a1.y - b1.y, dz1 = a1.z - b1.z, dw1 = a1.w - b1.w;
            acc = fmaf(w.x, dx0 * dx0 + dy0 * dy0 + dz0 * dz0 + dw0 * dw0, acc);
            acc = fmaf(w.y, dx1 * dx1 + dy1 * dy1 + dz1 * dz1 + dw1 * dw1, acc);
        }
    }

    // ---- single-edge tail (p odd; at most 1 edge) ----
    int t = blockIdx.x * blockDim.x + tid;
    int stride = gridDim.x * blockDim.x;
    for (int k = npairs * 2 + t; k < p; k += stride) {
        int2 e = __ldg(&etail[k]);
        float4 a = __ldg(&X[e.x]);
        float4 b = __ldg(&X[e.y]);
        float dx = a.x - b.x, dy = a.y - b.y, dz = a.z - b.z, dw = a.w - b.w;
        acc = fmaf(__ldg(&wtail[k]), dx * dx + dy * dy + dz * dz + dw * dw, acc);
    }

    // ---- fused reduction ----
    #pragma unroll
    for (int off = 16; off > 0; off >>= 1)
        acc += __shfl_down_sync(0xffffffffu, acc, off);

    __shared__ float warp_sums[8];
    if (lane == 0) warp_sums[wid] = acc;
    __syncthreads();

    __shared__ bool is_last;
    if (wid == 0) {
        float v = (lane < 8) ? warp_sums[lane] : 0.0f;
        #pragma unroll
        for (int off = 4; off > 0; off >>= 1)
            v += __shfl_down_sync(0xffffffffu, v, off);
        if (lane == 0) {
            g_partials[blockIdx.x] = v;
            __threadfence();
            unsigned int done = atomicInc(&g_ticket, gridDim.x - 1);
            is_last = (done == gridDim.x - 1);   // wraps ticket back to 0
        }
    }
    __syncthreads();

    if (is_last) {
        if (tid == 0) g_ctr = 0;   // all grabs finished before any ticket arrives
        double s = 0.0;
        for (int i = tid; i < (int)gridDim.x; i += blockDim.x)
            s += (double)g_partials[i];
        __shared__ double dsums[8];
        #pragma unroll
        for (int off = 16; off > 0; off >>= 1)
            s += __shfl_down_sync(0xffffffffu, s, off);
        if (lane == 0) dsums[wid] = s;
        __syncthreads();
        if (wid == 0) {
            double v = (lane < 8) ? dsums[lane] : 0.0;
            #pragma unroll
            for (int off = 4; off > 0; off >>= 1)
                v += __shfl_down_sync(0xffffffffu, v, off);
            if (lane == 0)
                out[0] = (float)(v * (double)inv_p);
        }
    }
}

extern "C" void kernel_launch(void* const* d_in, const int* in_sizes, int n_in,
                              void* d_out, int out_size) {
    // Inputs: X (f32, 1M x 4), edges (int32, 10M x 2), weights (f32, 10M)
    const float4* X     = (const float4*)d_in[0];
    const int*    edges = (const int*)d_in[1];
    const float*  w     = (const float*)d_in[2];
    float*        out   = (float*)d_out;

    int p = in_sizes[2];
    int npairs = p / 2;
    int nchunks = (npairs + CHUNK_PAIRS - 1) / CHUNK_PAIRS;

    int blocks = 1184;   // 148 SMs x 8 CTAs, 64 warps/SM (proven L1tex-ceiling config)
    if (blocks > MAX_BLOCKS) blocks = MAX_BLOCKS;

    mde_steal_kernel<<<blocks, 256>>>(X,
                                      (const int4*)edges, (const float2*)w,
                                      npairs, nchunks,
                                      (const int2*)edges, w, p,
                                      out, 1.0f / (float)p);
}